// round 6
// baseline (speedup 1.0000x reference)
#include <cuda_runtime.h>
#include <cstdint>
#include <math.h>

#define PTS    8192
#define NB     4
#define NSETS  8               // (batch, set): even = yhat, odd = y
#define NX     64
#define NY     64
#define NCELL  (NX * NY)       // 4096 cells, row-major in y
#define GMIN   (-8.0f)
#define GINV   4.0f            // 1 / 0.25
#define PAD    128
#define ARR    (PTS + 2 * PAD) // 8448
#define BLKS_PER 16
#define NQBLK  (NSETS * BLKS_PER)  // 128 search blocks

// Cell-sorted points: [PAD pads][PTS points][PAD pads].
// .w = |p|^2 for real points; pads are (0,0,0,3e38) so they never win a min.
__device__ float4 g_pts[NSETS][ARR];
__device__ int    g_hist[NSETS][NCELL];
__device__ int    g_start[NSETS][NCELL + 1];
__device__ int    g_cursor[NSETS][NCELL];
__device__ float  g_part[NQBLK];

__device__ __forceinline__ int cell_of(float x, float y) {
    int bx = min(max((int)((x - GMIN) * GINV), 0), NX - 1);
    int by = min(max((int)((y - GMIN) * GINV), 0), NY - 1);
    return by * NX + bx;
}

// ---------------------------------------------------------------------------
__global__ void zero_kernel() {
    int i = blockIdx.x * blockDim.x + threadIdx.x;   // 32768 = 8*4096
    ((int*)g_hist)[i] = 0;
}

// 128 blocks x 512 : one point per thread, count cells
__global__ __launch_bounds__(512)
void hist_kernel(const float* __restrict__ yhat, const float* __restrict__ y)
{
    int gid = blockIdx.x * 512 + threadIdx.x;     // 0..65535
    int g = gid >> 13, i = gid & 8191;
    const float* src = ((g & 1) ? y : yhat) + (size_t)(g >> 1) * PTS * 3;
    float x = src[3 * i], yy = src[3 * i + 1];
    atomicAdd(&g_hist[g][cell_of(x, yy)], 1);
}

// 8 blocks (one per set) x 512 : exclusive scan of 4096 cells, init cursors,
// write sentinel + pads.
__global__ __launch_bounds__(512)
void scan_kernel()
{
    __shared__ int wsum[16];
    const int g = blockIdx.x, t = threadIdx.x;
    const int base = t * 8;
    int v[8], tot = 0;
#pragma unroll
    for (int j = 0; j < 8; ++j) { v[j] = g_hist[g][base + j]; tot += v[j]; }

    const int lane = t & 31, warp = t >> 5;
    int inc = tot;
#pragma unroll
    for (int o = 1; o < 32; o <<= 1) {
        int u = __shfl_up_sync(0xffffffffu, inc, o);
        if (lane >= o) inc += u;
    }
    if (lane == 31) wsum[warp] = inc;
    __syncthreads();
    if (warp == 0) {
        int wv = (lane < 16) ? wsum[lane] : 0;
#pragma unroll
        for (int o = 1; o < 16; o <<= 1) {
            int u = __shfl_up_sync(0xffffffffu, wv, o);
            if (lane >= o) wv += u;
        }
        if (lane < 16) wsum[lane] = wv;
    }
    __syncthreads();
    int excl = inc - tot + ((warp > 0) ? wsum[warp - 1] : 0);
#pragma unroll
    for (int j = 0; j < 8; ++j) {
        g_start[g][base + j]  = excl;
        g_cursor[g][base + j] = excl;
        excl += v[j];
    }
    if (t == 0) g_start[g][NCELL] = PTS;
    if (t < PAD) {
        float4 padv = make_float4(0.f, 0.f, 0.f, 3.0e38f);
        g_pts[g][t]             = padv;
        g_pts[g][PAD + PTS + t] = padv;
    }
}

// 128 blocks x 512 : scatter points into cell order (|p|^2 in .w).
// Within-cell order nondeterministic; final exact-min output is order-indep.
__global__ __launch_bounds__(512)
void scatter_kernel(const float* __restrict__ yhat, const float* __restrict__ y)
{
    int gid = blockIdx.x * 512 + threadIdx.x;
    int g = gid >> 13, i = gid & 8191;
    const float* src = ((g & 1) ? y : yhat) + (size_t)(g >> 1) * PTS * 3;
    float x = src[3 * i], yy = src[3 * i + 1], z = src[3 * i + 2];
    int pos = atomicAdd(&g_cursor[g][cell_of(x, yy)], 1);
    float s = x * x + yy * yy + z * z;
    g_pts[g][PAD + pos] = make_float4(x, yy, z, s);
}

// ---------------------------------------------------------------------------
// search: warp-cooperative exact NN with 2D cell pruning, vote-free.
//   bestm = min over p of (|p|^2 - 2 q.p);  d^2 = bestm + |q|^2 (clamped).
//   Phase 1: fixed +/-64 cell-sorted points around warp's cell start.
//   Window:  r = sqrt(max-lane clamp(best+|q|^2,0)); cell box from lane
//            min/max (x,y) +- r. Any excluded cell has per-axis edge gap
//            >= r >= sqrt(best_lane) for every lane -> cannot win. Exact.
//   Phase 2: per y-row contiguous run scan, no votes.
// ---------------------------------------------------------------------------
__global__ __launch_bounds__(512)
void search_kernel()
{
    extern __shared__ float4 sp[];   // ARR entries
    const int bid = blockIdx.x;
    const int grp = bid / BLKS_PER;  // (b, set) 0..7
    const int sub = bid % BLKS_PER;
    const int qset = grp;
    const int pset = grp ^ 1;

    const int t = threadIdx.x;
    for (int i = t; i < ARR; i += 512)
        sp[i] = g_pts[pset][i];
    __syncthreads();

    const int warp = t >> 5, lane = t & 31;
    const int qi = (warp * BLKS_PER + sub) * 32 + lane;

    float4 q = g_pts[qset][PAD + qi];
    const float qx = q.x, qy = q.y;
    const float m2x = -2.f * q.x, m2y = -2.f * q.y, m2z = -2.f * q.z;
    const float sqq = q.w;

    // warp's anchor cell from lane 16 (queries are cell-coherent)
    float cx = __shfl_sync(0xffffffffu, qx, 16);
    float cy = __shfl_sync(0xffffffffu, qy, 16);
    const int k0 = PAD + g_start[pset][cell_of(cx, cy)];

    float bestA = 3.0e38f, bestB = 3.0e38f;

#define PROC4(baseidx) do {                                              \
        int _k = (baseidx);                                              \
        float4 p0 = sp[_k], p1 = sp[_k + 1], p2 = sp[_k + 2], p3 = sp[_k + 3]; \
        float d0 = fmaf(m2z, p0.z, fmaf(m2y, p0.y, fmaf(m2x, p0.x, p0.w))); \
        float d1 = fmaf(m2z, p1.z, fmaf(m2y, p1.y, fmaf(m2x, p1.x, p1.w))); \
        float d2 = fmaf(m2z, p2.z, fmaf(m2y, p2.y, fmaf(m2x, p2.x, p2.w))); \
        float d3 = fmaf(m2z, p3.z, fmaf(m2y, p3.y, fmaf(m2x, p3.x, p3.w))); \
        bestA = fminf(bestA, d0); bestB = fminf(bestB, d1);              \
        bestA = fminf(bestA, d2); bestB = fminf(bestB, d3);              \
    } while (0)

    // ---- phase 1: fixed 128 points around k0 (always >=64 real points) ----
#pragma unroll 4
    for (int g4 = 0; g4 < 32; ++g4) PROC4(k0 - 64 + 4 * g4);

    // ---- window from phase-1 best ----
    float r2 = fmaxf(fminf(bestA, bestB) + sqq, 0.f);
    float xmn = qx, xmx = qx, ymn = qy, ymx = qy;
#pragma unroll
    for (int o = 16; o > 0; o >>= 1) {
        r2  = fmaxf(r2,  __shfl_xor_sync(0xffffffffu, r2,  o));
        xmn = fminf(xmn, __shfl_xor_sync(0xffffffffu, xmn, o));
        xmx = fmaxf(xmx, __shfl_xor_sync(0xffffffffu, xmx, o));
        ymn = fminf(ymn, __shfl_xor_sync(0xffffffffu, ymn, o));
        ymx = fmaxf(ymx, __shfl_xor_sync(0xffffffffu, ymx, o));
    }
    float r = sqrtf(r2);
    int bx0 = min(max((int)((xmn - r - GMIN) * GINV), 0), NX - 1);
    int bx1 = min(max((int)((xmx + r - GMIN) * GINV), 0), NX - 1);
    int by0 = min(max((int)((ymn - r - GMIN) * GINV), 0), NY - 1);
    int by1 = min(max((int)((ymx + r - GMIN) * GINV), 0), NY - 1);

    // ---- phase 2: row-run scans (overlap with phase 1 is harmless) ----
    for (int by = by0; by <= by1; ++by) {
        int is = PAD + g_start[pset][by * NX + bx0];
        int ie = PAD + g_start[pset][by * NX + bx1 + 1];
#pragma unroll 2
        for (int k = is; k < ie; k += 4) PROC4(k);
    }

    float best = fmaxf(fminf(bestA, bestB) + sqq, 0.f);

    // block sum of mins (deterministic set of values)
#pragma unroll
    for (int o = 16; o > 0; o >>= 1)
        best += __shfl_down_sync(0xffffffffu, best, o);
    __shared__ float bsum[16];
    if (lane == 0) bsum[warp] = best;
    __syncthreads();
    if (t == 0) {
        float s = 0.f;
#pragma unroll
        for (int w = 0; w < 16; ++w) s += bsum[w];
        g_part[bid] = s;
    }
}

// loss = sum(all 2*B*PTS mins) / (B*PTS);  out = sqrt(0.5 * loss)
__global__ void final_kernel(float* __restrict__ out)
{
    const int t = threadIdx.x;   // 128
    double s = (double)g_part[t];
#pragma unroll
    for (int o = 16; o > 0; o >>= 1)
        s += __shfl_down_sync(0xffffffffu, s, o);
    __shared__ double sh[4];
    if ((t & 31) == 0) sh[t >> 5] = s;
    __syncthreads();
    if (t == 0) {
        double tot = sh[0] + sh[1] + sh[2] + sh[3];
        out[0] = (float)sqrt(0.5 * tot / (double)(NB * PTS));
    }
}

extern "C" void kernel_launch(void* const* d_in, const int* in_sizes, int n_in,
                              void* d_out, int out_size)
{
    const float* yhat = (const float*)d_in[0];   // [B, N, 3]
    const float* y    = (const float*)d_in[1];   // [B, M, 3]
    (void)in_sizes; (void)n_in; (void)out_size;

    cudaFuncSetAttribute(search_kernel,
                         cudaFuncAttributeMaxDynamicSharedMemorySize,
                         ARR * (int)sizeof(float4));

    zero_kernel<<<32, 1024>>>();
    hist_kernel<<<128, 512>>>(yhat, y);
    scan_kernel<<<NSETS, 512>>>();
    scatter_kernel<<<128, 512>>>(yhat, y);
    search_kernel<<<NQBLK, 512, ARR * sizeof(float4)>>>();
    final_kernel<<<1, 128>>>((float*)d_out);
}